// round 5
// baseline (speedup 1.0000x reference)
#include <cuda_runtime.h>
#include <math.h>

typedef unsigned long long ull;

#define B      8
#define DIM    1024
#define HID    512
#define NB     16
#define SEQ    2048
#define TLEN   4096
#define NSTEPS (TLEN - SEQ)
#define NBLK   128
#define NTHR   512
#define KP     1028
#define ACT_SLOT (B * KP)

// barrier ids
#define BAR_A1 0
#define BAR_B1 1
#define BAR_A2 2
#define BAR_B2 3
#define BAR_A3 4
#define BAR_B3 5
#define BAR_DONE 6

// smem offsets (floats)
#define OFF_W1   0        // [8 j][2048 k]
#define OFF_W2   16384    // [8 i][1024 k]
#define OFF_W3   24576    // [4 m][1024 k]
#define OFF_ACT  28672    // 2 slots x [8 b][KP]
#define OFF_RED  45120    // 512
#define OFF_C1   45632    // 128
#define OFF_C2   45760    // 128
#define OFF_BAS  45888    // 128
#define OFF_BD1T 46016    // 128
#define OFF_BD1B 46144    // 128
#define OFF_G    46272    // 32
#define OFF_WC2  46304    // 64
#define OFF_BB   46368    // 40
#define SMEM_FLOATS 46408

// ---------------- persistent state ----------------
__device__ float g_h1[B * DIM];
__device__ float g_un[B * DIM];
__device__ float g_coef[2][B * NB];
__device__ unsigned int g_bar[8];   // monotonic counters; reset at kernel end

// ---------------- packed f32x2 FMA ----------------
__device__ __forceinline__ void fma2(ull& d, ull a, ull b) {
    asm("fma.rn.f32x2 %0, %1, %2, %0;" : "+l"(d) : "l"(a), "l"(b));
}
__device__ __forceinline__ float f2sum(ull v) {
    float lo, hi;
    asm("mov.b64 {%0,%1}, %2;" : "=f"(lo), "=f"(hi) : "l"(v));
    return lo + hi;
}

// ---------------- barrier primitives ----------------
__device__ __forceinline__ void bar_arrive(int i) {
    if (threadIdx.x == 0)
        asm volatile("red.release.gpu.global.add.u32 [%0], %1;"
                     :: "l"(&g_bar[i]), "r"(1u) : "memory");
}
__device__ __forceinline__ void bar_wait(int i, unsigned target) {
    if (threadIdx.x == 0) {
        unsigned v;
        do {
            asm volatile("ld.acquire.gpu.global.u32 %0, [%1];"
                         : "=r"(v) : "l"(&g_bar[i]) : "memory");
        } while (v < target);
    }
    __syncthreads();
}

// ---------------- prefix copy: out[:, 0:2048, :] = x ----------------
__global__ void copy_kernel(const float4* __restrict__ x4, float4* __restrict__ out4) {
    size_t q = (size_t)blockIdx.x * blockDim.x + threadIdx.x;
    int b = (int)(q >> 19);
    size_t r = q & 524287;
    out4[((size_t)b << 20) + r] = x4[q];
}

// ---------------- per-chain helpers (co = 0 for A, 4 for B) ----------------
__device__ __forceinline__ void prologue(float* sm, const float* __restrict__ out_dummy,
                                         float* __restrict__ out, int co, int s, int sA, int bid) {
    const int t = threadIdx.x;
    float* s_c1  = sm + OFF_C1;
    float* s_c2  = sm + OFF_C2;
    float* s_bas = sm + OFF_BAS;
    float* s_act = sm + OFF_ACT;
    float* s_bb  = sm + OFF_BB;
    if (t < 64) {
        int bb = co + (t >> 4), cc = t & 15;
        float b2v = s_bb[20 + cc];
        s_c1[bb * NB + cc] = (s >= 1) ? g_coef[1 - sA][bb * NB + cc] + b2v : 0.f;
        s_c2[bb * NB + cc] = (s >= 2) ? g_coef[sA][bb * NB + cc]     + b2v : 0.f;
    }
    __syncthreads();
    if (s > 0 && t < 32) {
        int b4 = t >> 3, il = t & 7;
        int bb = co + b4, ig = bid * 8 + il;
        float corr = 0.f;
        #pragma unroll
        for (int c = 0; c < NB; ++c) corr += s_c1[bb * NB + c] * s_bas[c * 8 + il];
        float v = s_act[(1 - sA) * ACT_SLOT + bb * KP + ig] + 0.1f * corr;
        out[((size_t)bb * TLEN + SEQ + s - 1) * DIM + ig] = v;
    }
}

__device__ __forceinline__ void phase1(float* sm, int co, int sA, int bid) {
    const int t = threadIdx.x;
    const int b4 = t & 3, kg = t >> 2;
    float* s_w1   = sm + OFF_W1;
    float* s_act  = sm + OFF_ACT;
    float* s_red  = sm + OFF_RED;
    float* s_c1   = sm + OFF_C1;
    float* s_c2   = sm + OFF_C2;
    float* s_bd1t = sm + OFF_BD1T;
    float* s_bd1b = sm + OFF_BD1B;
    float* s_bb   = sm + OFF_BB;
    const float* actA = s_act + (1 - sA) * ACT_SLOT + (co + b4) * KP;   // n_{s-1}
    const float* actB = s_act + sA * ACT_SLOT + (co + b4) * KP;         // n_{s-2}
    ull acc[8];
    #pragma unroll
    for (int j = 0; j < 8; ++j) acc[j] = 0ull;
    #pragma unroll
    for (int q = 0; q < 4; ++q) {
        const float* act = (q < 2) ? actA : actB;
        const int ka = (q & 1) * 512 + kg * 4;
        const int kw = q * 512 + kg * 4;
        ulonglong2 a = *reinterpret_cast<const ulonglong2*>(act + ka);
        #pragma unroll
        for (int jl = 0; jl < 8; ++jl) {
            ulonglong2 w = *reinterpret_cast<const ulonglong2*>(s_w1 + jl * 2048 + kw);
            fma2(acc[jl], w.x, a.x);
            fma2(acc[jl], w.y, a.y);
        }
    }
    float r[8];
    #pragma unroll
    for (int jl = 0; jl < 8; ++jl) {
        r[jl] = f2sum(acc[jl]);
        r[jl] += __shfl_xor_sync(0xffffffffu, r[jl], 4);
        r[jl] += __shfl_xor_sync(0xffffffffu, r[jl], 8);
        r[jl] += __shfl_xor_sync(0xffffffffu, r[jl], 16);
    }
    if ((t & 31) < 4) {
        int w = t >> 5;
        #pragma unroll
        for (int jl = 0; jl < 8; ++jl) s_red[(w * 4 + b4) * 8 + jl] = r[jl];
    }
    __syncthreads();
    if (t < 32) {
        int rb = t >> 3, jl = t & 7;
        float sum = 0.f;
        #pragma unroll
        for (int w = 0; w < 16; ++w) sum += s_red[(w * 4 + rb) * 8 + jl];
        int bb = co + rb;
        float cd = 0.f;
        #pragma unroll
        for (int c = 0; c < NB; ++c)
            cd += s_c1[bb * NB + c] * s_bd1t[c * 8 + jl]
                + s_c2[bb * NB + c] * s_bd1b[c * 8 + jl];
        float z = sum + 0.1f * cd + s_bb[jl];
        g_h1[bb * DIM + bid * 8 + jl] = tanhf(z);
    }
    __syncthreads();
}

__device__ __forceinline__ void stage4(float* dst_slot, const float* __restrict__ src, int co) {
    const int t = threadIdx.x;
    #pragma unroll
    for (int r = 0; r < 2; ++r) {
        int g = r * NTHR + t;                 // 0..1023 float4 indices
        int bb = co + (g >> 8), kq = g & 255;
        float4 v = *reinterpret_cast<const float4*>(src + bb * DIM + kq * 4);
        *reinterpret_cast<float4*>(dst_slot + bb * KP + kq * 4) = v;
    }
}

__device__ __forceinline__ void phase2(float* sm, int co, int sA, int bid) {
    const int t = threadIdx.x;
    const int b4 = t & 3, kg = t >> 2;
    float* s_w2  = sm + OFF_W2;
    float* s_act = sm + OFF_ACT;
    float* s_red = sm + OFF_RED;
    float* s_c1  = sm + OFF_C1;
    float* s_bas = sm + OFF_BAS;
    float* s_bb  = sm + OFF_BB;
    const float* act = s_act + sA * ACT_SLOT + (co + b4) * KP;          // h1
    ull acc[8];
    #pragma unroll
    for (int j = 0; j < 8; ++j) acc[j] = 0ull;
    #pragma unroll
    for (int q = 0; q < 2; ++q) {
        const int kk = q * 512 + kg * 4;
        ulonglong2 a = *reinterpret_cast<const ulonglong2*>(act + kk);
        #pragma unroll
        for (int il = 0; il < 8; ++il) {
            ulonglong2 w = *reinterpret_cast<const ulonglong2*>(s_w2 + il * 1024 + kk);
            fma2(acc[il], w.x, a.x);
            fma2(acc[il], w.y, a.y);
        }
    }
    float r[8];
    #pragma unroll
    for (int il = 0; il < 8; ++il) {
        r[il] = f2sum(acc[il]);
        r[il] += __shfl_xor_sync(0xffffffffu, r[il], 4);
        r[il] += __shfl_xor_sync(0xffffffffu, r[il], 8);
        r[il] += __shfl_xor_sync(0xffffffffu, r[il], 16);
    }
    if ((t & 31) < 4) {
        int w = t >> 5;
        #pragma unroll
        for (int il = 0; il < 8; ++il) s_red[(w * 4 + b4) * 8 + il] = r[il];
    }
    __syncthreads();
    if (t < 32) {
        int rb = t >> 3, il = t & 7;
        float sum = 0.f;
        #pragma unroll
        for (int w = 0; w < 16; ++w) sum += s_red[(w * 4 + rb) * 8 + il];
        int bb = co + rb, ig = bid * 8 + il;
        float corr = 0.f;
        #pragma unroll
        for (int c = 0; c < NB; ++c) corr += s_c1[bb * NB + c] * s_bas[c * 8 + il];
        float u = s_act[(1 - sA) * ACT_SLOT + bb * KP + ig] + 0.1f * corr + sum + s_bb[8 + il];
        g_un[bb * DIM + ig] = u;
    }
    __syncthreads();
}

__device__ __forceinline__ void phase3(float* sm, int co, int sA, int bid) {
    const int t = threadIdx.x;
    const int b4 = t & 3, kg = t >> 2;
    float* s_w3  = sm + OFF_W3;
    float* s_act = sm + OFF_ACT;
    float* s_red = sm + OFF_RED;
    float* s_g   = sm + OFF_G;
    float* s_wc2 = sm + OFF_WC2;
    float* s_bb  = sm + OFF_BB;
    const float* act = s_act + sA * ACT_SLOT + (co + b4) * KP;          // n_s
    ull acc[4];
    #pragma unroll
    for (int m = 0; m < 4; ++m) acc[m] = 0ull;
    #pragma unroll
    for (int q = 0; q < 2; ++q) {
        const int kk = q * 512 + kg * 4;
        ulonglong2 a = *reinterpret_cast<const ulonglong2*>(act + kk);
        #pragma unroll
        for (int ml = 0; ml < 4; ++ml) {
            ulonglong2 w = *reinterpret_cast<const ulonglong2*>(s_w3 + ml * 1024 + kk);
            fma2(acc[ml], w.x, a.x);
            fma2(acc[ml], w.y, a.y);
        }
    }
    float r[4];
    #pragma unroll
    for (int ml = 0; ml < 4; ++ml) {
        r[ml] = f2sum(acc[ml]);
        r[ml] += __shfl_xor_sync(0xffffffffu, r[ml], 4);
        r[ml] += __shfl_xor_sync(0xffffffffu, r[ml], 8);
        r[ml] += __shfl_xor_sync(0xffffffffu, r[ml], 16);
    }
    if ((t & 31) < 4) {
        int w = t >> 5;
        #pragma unroll
        for (int ml = 0; ml < 4; ++ml) s_red[(w * 4 + b4) * 4 + ml] = r[ml];
    }
    __syncthreads();
    if (t < 16) {
        int rb = t >> 2, ml = t & 3;
        float sum = 0.f;
        #pragma unroll
        for (int w = 0; w < 16; ++w) sum += s_red[(w * 4 + rb) * 4 + ml];
        float z = sum + s_bb[16 + ml];
        s_g[(co + rb) * 4 + ml] = 0.5f * z * (1.0f + erff(z * 0.70710678118654752f));
    }
    __syncthreads();
    if (t < 64) {
        int rb = t >> 4, cc = t & 15;
        int bb = co + rb;
        float a = 0.f;
        #pragma unroll
        for (int ml = 0; ml < 4; ++ml) a += s_g[bb * 4 + ml] * s_wc2[ml * NB + cc];
        atomicAdd(&g_coef[sA][bb * NB + cc], a);
    }
    __syncthreads();
}

// ---------------- persistent extrapolation kernel ----------------
__global__ void __launch_bounds__(NTHR, 1)
extrap_kernel(const float* __restrict__ x, const float* __restrict__ basis,
              const float* __restrict__ W1, const float* __restrict__ b1,
              const float* __restrict__ W2, const float* __restrict__ b2,
              const float* __restrict__ D1, const float* __restrict__ bD1,
              const float* __restrict__ D2, const float* __restrict__ bD2,
              float* __restrict__ out)
{
    extern __shared__ float sm[];
    float* s_w1   = sm + OFF_W1;
    float* s_w2   = sm + OFF_W2;
    float* s_w3   = sm + OFF_W3;
    float* s_act  = sm + OFF_ACT;
    float* s_bas  = sm + OFF_BAS;
    float* s_bd1t = sm + OFF_BD1T;
    float* s_bd1b = sm + OFF_BD1B;
    float* s_wc2  = sm + OFF_WC2;
    float* s_bb   = sm + OFF_BB;

    const int bid = blockIdx.x;
    const int t   = threadIdx.x;

    // ================= init: weights -> smem =================
    for (int idx = t; idx < 8 * 2048; idx += NTHR) {
        int jl = idx & 7, kk = idx >> 3;
        s_w1[jl * 2048 + kk] = __ldg(D1 + (size_t)kk * DIM + bid * 8 + jl);
    }
    for (int idx = t; idx < 8 * 1024; idx += NTHR) {
        int il = idx & 7, kk = idx >> 3;
        s_w2[il * 1024 + kk] = __ldg(D2 + (size_t)kk * DIM + bid * 8 + il);
    }
    for (int idx = t; idx < 4 * 1024; idx += NTHR) {
        int ml = idx & 3, kk = idx >> 2;
        s_w3[ml * 1024 + kk] = __ldg(W1 + (size_t)kk * HID + bid * 4 + ml);
    }
    if (t < 128) s_bas[t] = __ldg(basis + (size_t)(t >> 3) * DIM + bid * 8 + (t & 7));
    if (t < 64)  s_wc2[t] = __ldg(W2 + (size_t)(bid * 4 + (t >> 4)) * NB + (t & 15));
    if (t >= 64 && t < 72)        s_bb[t - 64]      = __ldg(bD1 + bid * 8 + (t - 64));
    else if (t >= 72 && t < 80)   s_bb[t - 72 + 8]  = __ldg(bD2 + bid * 8 + (t - 72));
    else if (t >= 80 && t < 84)   s_bb[t - 80 + 16] = __ldg(b1 + bid * 4 + (t - 80));
    else if (t >= 84 && t < 100)  s_bb[t - 84 + 20] = __ldg(b2 + (t - 84));
    // initial acts: slot1 = n_{-1} = x[:,SEQ-1], slot0 = n_{-2} = x[:,SEQ-2]
    for (int g = t; g < 2048; g += NTHR) {
        int bb = g >> 8, kq = g & 255;
        float4 v1 = *reinterpret_cast<const float4*>(x + ((size_t)bb * SEQ + SEQ - 1) * DIM + kq * 4);
        float4 v0 = *reinterpret_cast<const float4*>(x + ((size_t)bb * SEQ + SEQ - 2) * DIM + kq * 4);
        *reinterpret_cast<float4*>(s_act + ACT_SLOT + bb * KP + kq * 4) = v1;
        *reinterpret_cast<float4*>(s_act + bb * KP + kq * 4) = v0;
    }
    __syncthreads();
    // BD1t/BD1b = basis @ D1(top/bottom) for this block's 8 columns
    if (t < 256) {
        int half = t >> 7, c = (t >> 3) & 15, jl = t & 7;
        const float* wr = s_w1 + jl * 2048 + half * 1024;
        const float* br = basis + (size_t)c * DIM;
        float a0 = 0.f, a1 = 0.f, a2 = 0.f, a3 = 0.f;
        for (int k = 0; k < 1024; k += 4) {
            a0 += wr[k]     * __ldg(br + k);
            a1 += wr[k + 1] * __ldg(br + k + 1);
            a2 += wr[k + 2] * __ldg(br + k + 2);
            a3 += wr[k + 3] * __ldg(br + k + 3);
        }
        (half ? s_bd1b : s_bd1t)[c * 8 + jl] = (a0 + a1) + (a2 + a3);
    }
    __syncthreads();

    // ================= pipelined step loop (chains A=batches 0-3, B=4-7) =================
    for (int s = 0;; ++s) {
        const int sA = s & 1;
        const unsigned ts  = 128u * (unsigned)s;
        const unsigned ts1 = ts + 128u;

        if (s > 0) bar_wait(BAR_A3, ts);                 // coefA(s-1) ready
        prologue(sm, x, out, 0, s, sA, bid);
        if (s == NSTEPS) {
            if (s > 0) bar_wait(BAR_B3, ts);
            prologue(sm, x, out, 4, s, sA, bid);
            break;
        }
        __syncthreads();
        phase1(sm, 0, sA, bid);
        bar_arrive(BAR_A1);

        if (s > 0) bar_wait(BAR_B3, ts);                 // coefB(s-1) ready
        prologue(sm, x, out, 4, s, sA, bid);
        __syncthreads();
        phase1(sm, 4, sA, bid);
        bar_arrive(BAR_B1);

        bar_wait(BAR_A1, ts1);
        if (bid == 0 && t < 64) g_coef[sA][(t >> 4) * NB + (t & 15)] = 0.f;   // zero A rows
        stage4(sm + OFF_ACT + sA * ACT_SLOT, g_h1, 0);
        __syncthreads();
        phase2(sm, 0, sA, bid);
        bar_arrive(BAR_A2);

        bar_wait(BAR_B1, ts1);
        if (bid == 0 && t < 64) g_coef[sA][(4 + (t >> 4)) * NB + (t & 15)] = 0.f;  // zero B rows
        stage4(sm + OFF_ACT + sA * ACT_SLOT, g_h1, 4);
        __syncthreads();
        phase2(sm, 4, sA, bid);
        bar_arrive(BAR_B2);

        bar_wait(BAR_A2, ts1);
        stage4(sm + OFF_ACT + sA * ACT_SLOT, g_un, 0);
        __syncthreads();
        phase3(sm, 0, sA, bid);
        bar_arrive(BAR_A3);

        bar_wait(BAR_B2, ts1);
        stage4(sm + OFF_ACT + sA * ACT_SLOT, g_un, 4);
        __syncthreads();
        phase3(sm, 4, sA, bid);
        bar_arrive(BAR_B3);
    }

    // ================= done barrier + counter reset (replay safety) =================
    __syncthreads();
    if (t == 0) {
        asm volatile("red.release.gpu.global.add.u32 [%0], %1;"
                     :: "l"(&g_bar[BAR_DONE]), "r"(1u) : "memory");
        if (bid == 0) {
            unsigned v;
            do {
                asm volatile("ld.acquire.gpu.global.u32 %0, [%1];"
                             : "=r"(v) : "l"(&g_bar[BAR_DONE]) : "memory");
            } while (v < (unsigned)NBLK);
            #pragma unroll
            for (int i = 0; i < 8; ++i) g_bar[i] = 0;
        }
    }
}

// ---------------- launch ----------------
extern "C" void kernel_launch(void* const* d_in, const int* in_sizes, int n_in,
                              void* d_out, int out_size) {
    const float* x     = (const float*)d_in[0];
    const float* basis = (const float*)d_in[1];
    const float* W1    = (const float*)d_in[2];
    const float* b1    = (const float*)d_in[3];
    const float* W2    = (const float*)d_in[4];
    const float* b2v   = (const float*)d_in[5];
    const float* D1    = (const float*)d_in[6];
    const float* bD1   = (const float*)d_in[7];
    const float* D2    = (const float*)d_in[8];
    const float* bD2   = (const float*)d_in[9];
    float* out = (float*)d_out;

    copy_kernel<<<4096, 1024>>>((const float4*)x, (float4*)out);

    size_t smem_bytes = (size_t)SMEM_FLOATS * sizeof(float);   // ~181.3 KB
    cudaFuncSetAttribute(extrap_kernel, cudaFuncAttributeMaxDynamicSharedMemorySize,
                         (int)smem_bytes);
    extrap_kernel<<<NBLK, NTHR, smem_bytes>>>(x, basis, W1, b1, W2, b2v,
                                              D1, bD1, D2, bD2, out);
}

// round 6
// speedup vs baseline: 1.3775x; 1.3775x over previous
#include <cuda_runtime.h>
#include <math.h>

typedef unsigned long long ull;

#define B      8
#define DIM    1024
#define HID    512
#define NB     16
#define SEQ    2048
#define TLEN   4096
#define NSTEPS (TLEN - SEQ)
#define NBLK   128
#define NTHR   512

// barrier ids (monotonic counters)
#define BAR1 0   // h1 ready
#define BAR2 1   // n_s ready
#define BAR3 2   // coef_s ready
#define BARD 3   // done

// smem offsets (floats)
#define OFF_W1   0        // 16384: D1 slice [8 j][2048 k]
#define OFF_W2   16384    // 8192 : D2 slice [8 i][1024 k]
#define OFF_W3   24576    // 4096 : W1 slice [4 m][1024 k]
#define OFF_RED  28672    // 1024
#define OFF_CM1  29696    // 128   c_{s-1}+b2
#define OFF_CS   29824    // 128   c_s+b2
#define OFF_BAS  29952    // 128   basis[c][own 8 cols]
#define OFF_BD1T 30080    // 128   (basis@D1 top)[c][own 8 j]
#define OFF_BD1B 30208    // 128
#define OFF_G    30336    // 32    gelu vals
#define OFF_WC2  30368    // 64    W2 slice
#define OFF_BB   30432    // 40    biases
#define SMEM_FLOATS 30472 // ~119 KB

// ---------------- persistent state ----------------
__device__ float g_h1[B * DIM];
__device__ float g_un[2][B * DIM];       // n_s ping-pong (pre-correction state)
__device__ float g_coef[2][B * NB];      // raw coef accumulators (no b2)
__device__ unsigned int g_bar[4];        // monotonic; reset at kernel end

// ---------------- packed f32x2 FMA ----------------
__device__ __forceinline__ void fma2(ull& d, ull a, ull b) {
    asm("fma.rn.f32x2 %0, %1, %2, %0;" : "+l"(d) : "l"(a), "l"(b));
}
__device__ __forceinline__ float f2sum(ull v) {
    float lo, hi;
    asm("mov.b64 {%0,%1}, %2;" : "=f"(lo), "=f"(hi) : "l"(v));
    return lo + hi;
}

// ---------------- barrier primitives ----------------
__device__ __forceinline__ void bar_arrive(int i) {
    __syncthreads();
    if (threadIdx.x == 0)
        asm volatile("red.release.gpu.global.add.u32 [%0], %1;"
                     :: "l"(&g_bar[i]), "r"(1u) : "memory");
}
__device__ __forceinline__ void bar_wait(int i, unsigned target) {
    if (threadIdx.x == 0) {
        unsigned v;
        do {
            asm volatile("ld.acquire.gpu.global.u32 %0, [%1];"
                         : "=r"(v) : "l"(&g_bar[i]) : "memory");
        } while (v < target);
    }
    __syncthreads();
}

// ---------------- prefix copy: out[:, 0:2048, :] = x ----------------
__global__ void copy_kernel(const float4* __restrict__ x4, float4* __restrict__ out4) {
    size_t q = (size_t)blockIdx.x * blockDim.x + threadIdx.x;
    int b = (int)(q >> 19);
    size_t r = q & 524287;
    out4[((size_t)b << 20) + r] = x4[q];
}

// 8-accumulator matvec slice: acts from GLOBAL (LDG), weights from smem.
__device__ __forceinline__ void acc8(ull acc[8], const float* __restrict__ act_row,
                                     const float* s_w, int wstride, int woff, int kg) {
    #pragma unroll
    for (int q = 0; q < 4; ++q) {
        const int k = q * 256 + kg * 4;
        ulonglong2 a = *reinterpret_cast<const ulonglong2*>(act_row + k);
        #pragma unroll
        for (int jl = 0; jl < 8; ++jl) {
            ulonglong2 w = *reinterpret_cast<const ulonglong2*>(s_w + jl * wstride + woff + k);
            fma2(acc[jl], w.x, a.x);
            fma2(acc[jl], w.y, a.y);
        }
    }
}

// in-warp reduce 8 accs over kg-subgroups; lanes<8 write s_red[warp][b][8]
__device__ __forceinline__ void reduce8(float* s_red, ull acc[8], int t) {
    const int b = t & 7;
    #pragma unroll
    for (int jl = 0; jl < 8; ++jl) {
        float r = f2sum(acc[jl]);
        r += __shfl_xor_sync(0xffffffffu, r, 8);
        r += __shfl_xor_sync(0xffffffffu, r, 16);
        if ((t & 31) < 8) s_red[((t >> 5) * 8 + b) * 8 + jl] = r;
    }
}

// ---------------- persistent extrapolation kernel ----------------
__global__ void __launch_bounds__(NTHR, 1)
extrap_kernel(const float* __restrict__ x, const float* __restrict__ basis,
              const float* __restrict__ W1, const float* __restrict__ b1,
              const float* __restrict__ W2, const float* __restrict__ b2,
              const float* __restrict__ D1, const float* __restrict__ bD1,
              const float* __restrict__ D2, const float* __restrict__ bD2,
              float* __restrict__ out)
{
    extern __shared__ float sm[];
    float* s_w1   = sm + OFF_W1;
    float* s_w2   = sm + OFF_W2;
    float* s_w3   = sm + OFF_W3;
    float* s_red  = sm + OFF_RED;
    float* s_cm1  = sm + OFF_CM1;
    float* s_cs   = sm + OFF_CS;
    float* s_bas  = sm + OFF_BAS;
    float* s_bd1t = sm + OFF_BD1T;
    float* s_bd1b = sm + OFF_BD1B;
    float* s_g    = sm + OFF_G;
    float* s_wc2  = sm + OFF_WC2;
    float* s_bb   = sm + OFF_BB;

    const int bid = blockIdx.x;
    const int t   = threadIdx.x;
    const int b   = t & 7;
    const int kg  = t >> 3;                 // 0..63

    // ================= init: weights -> smem =================
    for (int idx = t; idx < 8 * 2048; idx += NTHR) {
        int jl = idx & 7, kk = idx >> 3;
        s_w1[jl * 2048 + kk] = __ldg(D1 + (size_t)kk * DIM + bid * 8 + jl);
    }
    for (int idx = t; idx < 8 * 1024; idx += NTHR) {
        int il = idx & 7, kk = idx >> 3;
        s_w2[il * 1024 + kk] = __ldg(D2 + (size_t)kk * DIM + bid * 8 + il);
    }
    for (int idx = t; idx < 4 * 1024; idx += NTHR) {
        int ml = idx & 3, kk = idx >> 2;
        s_w3[ml * 1024 + kk] = __ldg(W1 + (size_t)kk * HID + bid * 4 + ml);
    }
    if (t < 128) s_bas[t] = __ldg(basis + (size_t)(t >> 3) * DIM + bid * 8 + (t & 7));
    if (t < 64)  s_wc2[t] = __ldg(W2 + (size_t)(bid * 4 + (t >> 4)) * NB + (t & 15));
    if (t >= 64 && t < 72)        s_bb[t - 64]      = __ldg(bD1 + bid * 8 + (t - 64));
    else if (t >= 72 && t < 80)   s_bb[t - 72 + 8]  = __ldg(bD2 + bid * 8 + (t - 72));
    else if (t >= 80 && t < 84)   s_bb[t - 80 + 16] = __ldg(b1 + bid * 4 + (t - 80));
    else if (t >= 84 && t < 100)  s_bb[t - 84 + 20] = __ldg(b2 + (t - 84));
    if (bid == 0 && t >= 128 && t < 256) g_coef[1][t - 128] = 0.f;   // c_{-1} = 0
    __syncthreads();

    // BD1t/BD1b = basis @ D1(top/bottom) for this block's 8 j columns
    if (t < 256) {
        int half = t >> 7, c = (t >> 3) & 15, jl = t & 7;
        const float* wr = s_w1 + jl * 2048 + half * 1024;
        const float* br = basis + (size_t)c * DIM;
        float a0 = 0.f, a1 = 0.f, a2 = 0.f, a3 = 0.f;
        for (int k = 0; k < 1024; k += 4) {
            a0 += wr[k]     * __ldg(br + k);
            a1 += wr[k + 1] * __ldg(br + k + 1);
            a2 += wr[k + 2] * __ldg(br + k + 2);
            a3 += wr[k + 3] * __ldg(br + k + 3);
        }
        (half ? s_bd1b : s_bd1t)[c * 8 + jl] = (a0 + a1) + (a2 + a3);
    }
    __syncthreads();

    // ================= preloop: h1_0 from x rows (corrections are exactly 0) =================
    {
        const float* rA = x + ((size_t)b * SEQ + SEQ - 1) * DIM;   // n_{-1}
        const float* rB = x + ((size_t)b * SEQ + SEQ - 2) * DIM;   // n_{-2}
        ull acc[8];
        #pragma unroll
        for (int j = 0; j < 8; ++j) acc[j] = 0ull;
        acc8(acc, rA, s_w1, 2048, 0,    kg);
        acc8(acc, rB, s_w1, 2048, 1024, kg);
        reduce8(s_red, acc, t);
    }
    __syncthreads();
    if (t < 64) {
        int bb = t >> 3, jl = t & 7;
        float sum = 0.f;
        #pragma unroll
        for (int w = 0; w < 16; ++w) sum += s_red[(w * 8 + bb) * 8 + jl];
        g_h1[bb * DIM + bid * 8 + jl] = tanhf(sum + s_bb[jl]);
    }
    bar_arrive(BAR1);

    // ================= step loop =================
    for (int s = 0; s < NSTEPS; ++s) {
        const int sA = s & 1;
        const unsigned tgt = (unsigned)(s + 1) * NBLK;

        // ---- wait h1_s; stage c_{s-1}+b2; zero c_s accumulator ----
        bar_wait(BAR1, tgt);
        if (t < 128) {
            float b2v = s_bb[20 + (t & 15)];
            s_cm1[t] = (s >= 1) ? g_coef[1 - sA][t] + b2v : 0.f;
        }
        if (bid == 0 && t >= 128 && t < 256) g_coef[sA][t - 128] = 0.f;

        // ================= P2: n_s = n_{s-1} + 0.1 c_{s-1}·basis + h1_s@D2 + bD2 =================
        {
            ull acc[8];
            #pragma unroll
            for (int j = 0; j < 8; ++j) acc[j] = 0ull;
            acc8(acc, g_h1 + b * DIM, s_w2, 1024, 0, kg);
            reduce8(s_red, acc, t);
        }
        __syncthreads();
        if (t < 64) {
            int bb = t >> 3, il = t & 7;
            int ig = bid * 8 + il;
            float sum = 0.f;
            #pragma unroll
            for (int w = 0; w < 16; ++w) sum += s_red[(w * 8 + bb) * 8 + il];
            float corr = 0.f;
            #pragma unroll
            for (int c = 0; c < NB; ++c) corr += s_cm1[bb * NB + c] * s_bas[c * 8 + il];
            float nprev = (s == 0) ? __ldg(x + ((size_t)bb * SEQ + SEQ - 1) * DIM + ig)
                                   : g_un[1 - sA][bb * DIM + ig];
            g_un[sA][bb * DIM + ig] = nprev + 0.1f * corr + sum + s_bb[8 + il];
        }
        bar_arrive(BAR2);

        // ---- P1_{s+1} half B: n_{s-1}@D1(bottom) — old data, overlaps bar2 wakeup ----
        ull acc1[8];
        #pragma unroll
        for (int j = 0; j < 8; ++j) acc1[j] = 0ull;
        {
            const float* rB = (s == 0) ? (x + ((size_t)b * SEQ + SEQ - 1) * DIM)
                                       : (g_un[1 - sA] + b * DIM);
            acc8(acc1, rB, s_w1, 2048, 1024, kg);
        }
        bar_wait(BAR2, tgt);

        // ================= P3: coef partials from n_s (4 m-cols/block) =================
        {
            const float* nrow = g_un[sA] + b * DIM;
            ull a4[4];
            #pragma unroll
            for (int m = 0; m < 4; ++m) a4[m] = 0ull;
            #pragma unroll
            for (int q = 0; q < 4; ++q) {
                const int k = q * 256 + kg * 4;
                ulonglong2 a = *reinterpret_cast<const ulonglong2*>(nrow + k);
                #pragma unroll
                for (int ml = 0; ml < 4; ++ml) {
                    ulonglong2 w = *reinterpret_cast<const ulonglong2*>(s_w3 + ml * 1024 + k);
                    fma2(a4[ml], w.x, a.x);
                    fma2(a4[ml], w.y, a.y);
                }
            }
            #pragma unroll
            for (int ml = 0; ml < 4; ++ml) {
                float r = f2sum(a4[ml]);
                r += __shfl_xor_sync(0xffffffffu, r, 8);
                r += __shfl_xor_sync(0xffffffffu, r, 16);
                if ((t & 31) < 8) s_red[((t >> 5) * 8 + b) * 4 + ml] = r;
            }
        }
        __syncthreads();
        if (t < 32) {
            int bb = t >> 2, ml = t & 3;
            float sum = 0.f;
            #pragma unroll
            for (int w = 0; w < 16; ++w) sum += s_red[(w * 8 + bb) * 4 + ml];
            float z = sum + s_bb[16 + ml];
            s_g[bb * 4 + ml] = 0.5f * z * (1.0f + erff(z * 0.70710678118654752f));
        }
        __syncthreads();
        if (t < 128) {
            int bb = t >> 4, cc = t & 15;
            float a = 0.f;
            #pragma unroll
            for (int ml = 0; ml < 4; ++ml) a += s_g[bb * 4 + ml] * s_wc2[ml * NB + cc];
            atomicAdd(&g_coef[sA][bb * NB + cc], a);
        }
        bar_arrive(BAR3);

        // ---- P1_{s+1} half A: n_s@D1(top) — hides bar3 latency ----
        acc8(acc1, g_un[sA] + b * DIM, s_w1, 2048, 0, kg);
        reduce8(s_red, acc1, t);

        bar_wait(BAR3, tgt);
        if (t < 128) s_cs[t] = g_coef[sA][t] + s_bb[20 + (t & 15)];
        __syncthreads();

        // ---- P1 tail: h1_{s+1} with folded corrections; output row SEQ+s ----
        if (t < 64) {
            int bb = t >> 3, jl = t & 7;
            float sum = 0.f;
            #pragma unroll
            for (int w = 0; w < 16; ++w) sum += s_red[(w * 8 + bb) * 8 + jl];
            float cd = 0.f;
            #pragma unroll
            for (int c = 0; c < NB; ++c)
                cd += s_cs[bb * NB + c]  * s_bd1t[c * 8 + jl]
                    + s_cm1[bb * NB + c] * s_bd1b[c * 8 + jl];
            g_h1[bb * DIM + bid * 8 + jl] = tanhf(sum + 0.1f * cd + s_bb[jl]);
        }
        if (t >= 64 && t < 80) {
            int tt = t - 64;
            int bb = tt >> 1, hf = tt & 1;
            int c0 = bid * 8 + hf * 4;
            float4 n = *reinterpret_cast<const float4*>(g_un[sA] + bb * DIM + c0);
            float o[4] = {n.x, n.y, n.z, n.w};
            #pragma unroll
            for (int xi = 0; xi < 4; ++xi) {
                float corr = 0.f;
                #pragma unroll
                for (int c = 0; c < NB; ++c)
                    corr += s_cs[bb * NB + c] * s_bas[c * 8 + hf * 4 + xi];
                o[xi] += 0.1f * corr;
            }
            *reinterpret_cast<float4*>(out + ((size_t)bb * TLEN + SEQ + s) * DIM + c0) =
                make_float4(o[0], o[1], o[2], o[3]);
        }
        bar_arrive(BAR1);
    }

    // ================= done barrier + counter reset (replay safety) =================
    __syncthreads();
    if (t == 0) {
        asm volatile("red.release.gpu.global.add.u32 [%0], %1;"
                     :: "l"(&g_bar[BARD]), "r"(1u) : "memory");
        if (bid == 0) {
            unsigned v;
            do {
                asm volatile("ld.acquire.gpu.global.u32 %0, [%1];"
                             : "=r"(v) : "l"(&g_bar[BARD]) : "memory");
            } while (v < (unsigned)NBLK);
            #pragma unroll
            for (int i = 0; i < 4; ++i) g_bar[i] = 0;
        }
    }
}

// ---------------- launch ----------------
extern "C" void kernel_launch(void* const* d_in, const int* in_sizes, int n_in,
                              void* d_out, int out_size) {
    const float* x     = (const float*)d_in[0];
    const float* basis = (const float*)d_in[1];
    const float* W1    = (const float*)d_in[2];
    const float* b1    = (const float*)d_in[3];
    const float* W2    = (const float*)d_in[4];
    const float* b2v   = (const float*)d_in[5];
    const float* D1    = (const float*)d_in[6];
    const float* bD1   = (const float*)d_in[7];
    const float* D2    = (const float*)d_in[8];
    const float* bD2   = (const float*)d_in[9];
    float* out = (float*)d_out;

    copy_kernel<<<4096, 1024>>>((const float4*)x, (float4*)out);

    size_t smem_bytes = (size_t)SMEM_FLOATS * sizeof(float);   // ~119 KB
    cudaFuncSetAttribute(extrap_kernel, cudaFuncAttributeMaxDynamicSharedMemorySize,
                         (int)smem_bytes);
    extrap_kernel<<<NBLK, NTHR, smem_bytes>>>(x, basis, W1, b1, W2, b2v,
                                              D1, bD1, D2, bD2, out);
}